// round 11
// baseline (speedup 1.0000x reference)
#include <cuda_runtime.h>

#define P_DIM 512
#define Q_DIM 64
#define B_DIM 16
#define E_DIM 256
#define H_DIM 256
#define O_DIM 256

// ---------------- scratch (static __device__, no allocation) ----------------
__device__ float g_Wp[P_DIM * B_DIM * H_DIM];          // (P,B,H)
__device__ float g_Wq[Q_DIM * B_DIM * H_DIM];          // (Q,B,H)
__device__ float g_gcat[P_DIM * B_DIM * 2 * E_DIM];    // (P,B,2E) = [passage | c]
__device__ float g_cg[P_DIM * B_DIM * E_DIM];          // c_gated
__device__ float g_gi[P_DIM * B_DIM * 3 * O_DIM];      // gi = x@w_ih^T + b_ih

// ---------------- math helpers ----------------
__device__ __forceinline__ float fast_tanh(float x) {
    float e = __expf(2.f * x);
    return 1.f - __fdividef(2.f, e + 1.f);
}
__device__ __forceinline__ float fast_sigmoid(float x) {
    return __fdividef(1.f, 1.f + __expf(-x));
}
__device__ __forceinline__ unsigned smem_u32(const void* p) {
    return (unsigned)__cvta_generic_to_shared(p);
}
__device__ __forceinline__ void fma_f32x2(unsigned long long& acc,
                                          unsigned long long a,
                                          unsigned long long b) {
    asm("fma.rn.f32x2 %0, %1, %2, %0;" : "+l"(acc) : "l"(a), "l"(b));
}
__device__ __forceinline__ unsigned long long dup_f32x2(float x) {
    unsigned long long r;
    asm("mov.b64 %0, {%1,%1};" : "=l"(r) : "f"(x));
    return r;
}

// ---------------- GEMM v3: C[M,N] = epi(A[M,K] @ W[N,K]^T), f32x2, 128x64x16 -------
// W stored in smem PRE-DUPLICATED as (w,w) u64 pairs -> inner loop has zero dup
// movs: per k-iter 4x LDS.128 + 16 FFMA2.
// MODE 0: raw    MODE 1: + bias[n]    MODE 2: sigmoid(acc) * aux[row*512 + 256 + n]
template <int MODE>
__global__ __launch_bounds__(256) void gemm_kernel(
    const float* __restrict__ A, const float* __restrict__ W,
    const float* __restrict__ bias, const float* __restrict__ aux,
    float* __restrict__ C, int M, int N, int K)
{
    __shared__ __align__(16) float As[2][16 * 132];                 // [k][m], stride 132
    __shared__ __align__(16) unsigned long long Wsd[2][16 * 66];    // [k][n] dup'd, stride 66

    const int tid = threadIdx.x;
    const int m0 = blockIdx.x * 128;
    const int n0 = blockIdx.y * 64;
    const int tm = tid >> 4;    // 0..15 -> rows tm*8..+8
    const int tn = tid & 15;    // cols tn*4..+4
    const int K4 = K >> 2;
    const int NT = K >> 4;      // number of 16-wide k tiles

    const int ra = tid >> 2;            // 0..63  (A rows ra, ra+64; W row ra)
    const int ca = tid & 3;             // float4 within 16-wide k tile
    const int kkA = ca * 4;

    unsigned long long acc2[4][4];
#pragma unroll
    for (int i = 0; i < 4; i++)
#pragma unroll
        for (int j = 0; j < 4; j++) acc2[i][j] = 0ull;

    const float4* A4 = (const float4*)A;
    const float4* W4 = (const float4*)W;

    float4 pa0, pa1, pw;
    pa0 = A4[(long)(m0 + ra) * K4 + ca];
    pa1 = A4[(long)(m0 + ra + 64) * K4 + ca];
    pw  = W4[(long)(n0 + ra) * K4 + ca];
    {
        As[0][(kkA + 0) * 132 + ra] = pa0.x; As[0][(kkA + 1) * 132 + ra] = pa0.y;
        As[0][(kkA + 2) * 132 + ra] = pa0.z; As[0][(kkA + 3) * 132 + ra] = pa0.w;
        As[0][(kkA + 0) * 132 + ra + 64] = pa1.x; As[0][(kkA + 1) * 132 + ra + 64] = pa1.y;
        As[0][(kkA + 2) * 132 + ra + 64] = pa1.z; As[0][(kkA + 3) * 132 + ra + 64] = pa1.w;
        Wsd[0][(kkA + 0) * 66 + ra] = dup_f32x2(pw.x);
        Wsd[0][(kkA + 1) * 66 + ra] = dup_f32x2(pw.y);
        Wsd[0][(kkA + 2) * 66 + ra] = dup_f32x2(pw.z);
        Wsd[0][(kkA + 3) * 66 + ra] = dup_f32x2(pw.w);
    }
    __syncthreads();

    for (int t = 0; t < NT; t++) {
        const int cur = t & 1, nxt = cur ^ 1;
        if (t + 1 < NT) {
            int kb = (t + 1) * 4;
            pa0 = A4[(long)(m0 + ra) * K4 + kb + ca];
            pa1 = A4[(long)(m0 + ra + 64) * K4 + kb + ca];
            pw  = W4[(long)(n0 + ra) * K4 + kb + ca];
        }
#pragma unroll
        for (int k = 0; k < 16; k++) {
            const ulonglong2* Ar =
                (const ulonglong2*)&As[cur][k * 132 + tm * 8];
            ulonglong2 a01 = Ar[0];     // m-pairs (0,1),(2,3)
            ulonglong2 a23 = Ar[1];     // m-pairs (4,5),(6,7)
            const ulonglong2* Wr =
                (const ulonglong2*)&Wsd[cur][k * 66 + tn * 4];
            ulonglong2 w01 = Wr[0];     // (w0,w0),(w1,w1)
            ulonglong2 w23 = Wr[1];     // (w2,w2),(w3,w3)
            fma_f32x2(acc2[0][0], a01.x, w01.x); fma_f32x2(acc2[0][1], a01.x, w01.y);
            fma_f32x2(acc2[0][2], a01.x, w23.x); fma_f32x2(acc2[0][3], a01.x, w23.y);
            fma_f32x2(acc2[1][0], a01.y, w01.x); fma_f32x2(acc2[1][1], a01.y, w01.y);
            fma_f32x2(acc2[1][2], a01.y, w23.x); fma_f32x2(acc2[1][3], a01.y, w23.y);
            fma_f32x2(acc2[2][0], a23.x, w01.x); fma_f32x2(acc2[2][1], a23.x, w01.y);
            fma_f32x2(acc2[2][2], a23.x, w23.x); fma_f32x2(acc2[2][3], a23.x, w23.y);
            fma_f32x2(acc2[3][0], a23.y, w01.x); fma_f32x2(acc2[3][1], a23.y, w01.y);
            fma_f32x2(acc2[3][2], a23.y, w23.x); fma_f32x2(acc2[3][3], a23.y, w23.y);
        }
        if (t + 1 < NT) {
            As[nxt][(kkA + 0) * 132 + ra] = pa0.x; As[nxt][(kkA + 1) * 132 + ra] = pa0.y;
            As[nxt][(kkA + 2) * 132 + ra] = pa0.z; As[nxt][(kkA + 3) * 132 + ra] = pa0.w;
            As[nxt][(kkA + 0) * 132 + ra + 64] = pa1.x; As[nxt][(kkA + 1) * 132 + ra + 64] = pa1.y;
            As[nxt][(kkA + 2) * 132 + ra + 64] = pa1.z; As[nxt][(kkA + 3) * 132 + ra + 64] = pa1.w;
            Wsd[nxt][(kkA + 0) * 66 + ra] = dup_f32x2(pw.x);
            Wsd[nxt][(kkA + 1) * 66 + ra] = dup_f32x2(pw.y);
            Wsd[nxt][(kkA + 2) * 66 + ra] = dup_f32x2(pw.z);
            Wsd[nxt][(kkA + 3) * 66 + ra] = dup_f32x2(pw.w);
        }
        __syncthreads();
    }

#pragma unroll
    for (int i2 = 0; i2 < 4; i2++) {
        float va[2][4];
#pragma unroll
        for (int j = 0; j < 4; j++)
            asm("mov.b64 {%0,%1}, %2;" : "=f"(va[0][j]), "=f"(va[1][j]) : "l"(acc2[i2][j]));
#pragma unroll
        for (int h = 0; h < 2; h++) {
            int row = m0 + tm * 8 + i2 * 2 + h;
            int col = n0 + tn * 4;
            float4 o;
            if (MODE == 0) {
                o = make_float4(va[h][0], va[h][1], va[h][2], va[h][3]);
            } else if (MODE == 1) {
                o = make_float4(va[h][0] + bias[col + 0], va[h][1] + bias[col + 1],
                                va[h][2] + bias[col + 2], va[h][3] + bias[col + 3]);
            } else {
                float4 g = *(const float4*)(aux + (long)row * 512 + 256 + col);
                o = make_float4(fast_sigmoid(va[h][0]) * g.x, fast_sigmoid(va[h][1]) * g.y,
                                fast_sigmoid(va[h][2]) * g.z, fast_sigmoid(va[h][3]) * g.w);
            }
            *(float4*)(&C[(long)row * N + col]) = o;
        }
    }
}

// ---------------- fused attention: scores -> softmax -> context -> concat ----------------
__global__ __launch_bounds__(256) void attn_kernel(
    const float* __restrict__ question, const float* __restrict__ passage,
    const float* __restrict__ v)
{
    __shared__ float wp[256];
    __shared__ float vv[256];
    __shared__ float sc[64];

    const int p = blockIdx.x;
    const int b = blockIdx.y;
    const int tid = threadIdx.x;
    const int w = tid >> 5, l = tid & 31;

    wp[tid] = g_Wp[((long)p * B_DIM + b) * H_DIM + tid];
    vv[tid] = v[tid];
    __syncthreads();

#pragma unroll
    for (int qi = 0; qi < 8; qi++) {
        int q = w * 8 + qi;
        const float* wq = &g_Wq[((long)q * B_DIM + b) * H_DIM];
        float acc = 0.f;
#pragma unroll
        for (int j = 0; j < 8; j++) {
            int h = l + 32 * j;
            acc += vv[h] * fast_tanh(wq[h] + wp[h]);
        }
#pragma unroll
        for (int s = 16; s > 0; s >>= 1) acc += __shfl_xor_sync(0xffffffffu, acc, s);
        if (l == 0) sc[q] = acc;
    }
    __syncthreads();

    if (w == 0) {
        float s0 = sc[l], s1 = sc[32 + l];
        float m = fmaxf(s0, s1);
#pragma unroll
        for (int s = 16; s > 0; s >>= 1) m = fmaxf(m, __shfl_xor_sync(0xffffffffu, m, s));
        float e0 = __expf(s0 - m), e1 = __expf(s1 - m);
        float sum = e0 + e1;
#pragma unroll
        for (int s = 16; s > 0; s >>= 1) sum += __shfl_xor_sync(0xffffffffu, sum, s);
        float inv = __fdividef(1.f, sum);
        sc[l] = e0 * inv;
        sc[32 + l] = e1 * inv;
    }
    __syncthreads();

    float acc = 0.f;
#pragma unroll
    for (int q = 0; q < 64; q++)
        acc += sc[q] * question[((long)q * B_DIM + b) * E_DIM + tid];

    float* gr = &g_gcat[((long)p * B_DIM + b) * 2 * E_DIM];
    gr[256 + tid] = acc;
    gr[tid] = passage[((long)p * B_DIM + b) * E_DIM + tid];
}

// ---------------- GRU v6 (716.9us winner, byte-exact): broadcast-LDS GEMV ----------
__global__ void __cluster_dims__(8, 1, 1) __launch_bounds__(256, 1)
gru_kernel(const float* __restrict__ gi, const float* __restrict__ w_hh,
           const float* __restrict__ b_hh, float* __restrict__ out)
{
    __shared__ __align__(16) unsigned long long hb64[2][260];  // 256 slots + 4 pad, 2080B stride
    __shared__ float part[8][3][32];                           // [srcWarp][gate][output]

    const int tid = threadIdx.x;
    const int w = tid >> 5;            // K-slice warp 0..7
    const int l = tid & 31;            // output lane
    const int b = blockIdx.x >> 3;     // batch
    const int rank = blockIdx.x & 7;   // cluster rank
    const int og = rank * 32 + l;      // global output index

    // ---- weights: rows {g*256+og}, cols [32w, 32w+32) -> 48 f32x2 regs ----
    unsigned long long wg2[3][16];
#pragma unroll
    for (int g = 0; g < 3; g++) {
        const float4* p4 = (const float4*)(w_hh + (long)(g * 256 + og) * 256 + w * 32);
#pragma unroll
        for (int i = 0; i < 8; i++) {
            float4 t = p4[i];
            asm("mov.b64 %0, {%1,%2};" : "=l"(wg2[g][2*i])   : "f"(t.x), "f"(t.y));
            asm("mov.b64 %0, {%1,%2};" : "=l"(wg2[g][2*i+1]) : "f"(t.z), "f"(t.w));
        }
    }
    const float b_r = b_hh[0 * 256 + og];
    const float b_z = b_hh[1 * 256 + og];
    const float b_n = b_hh[2 * 256 + og];

    for (int i = tid; i < 2 * 260; i += 256) ((unsigned long long*)hb64)[i] = 0ull;

    unsigned peerAddr[8];
    {
        unsigned laddr = smem_u32(&hb64[0][rank * 32 + l]);
#pragma unroll
        for (int c = 0; c < 8; c++)
            asm("mapa.shared::cluster.u32 %0, %1, %2;" : "=r"(peerAddr[c]) : "r"(laddr), "r"(c));
    }
    __syncthreads();
    asm volatile("barrier.cluster.arrive.aligned;" ::: "memory");
    asm volatile("barrier.cluster.wait.aligned;" ::: "memory");

    const unsigned hbBase = smem_u32(&hb64[0][0]);

    // gi pipeline (warp 0 only), one step ahead
    float gr_c = 0.f, gz_c = 0.f, gn_c = 0.f;
    if (w == 0) {
        long base = ((long)0 * B_DIM + b) * 768 + og;
        gr_c = gi[base]; gz_c = gi[base + 256]; gn_c = gi[base + 512];
    }

    for (int p = 0; p < P_DIM; p++) {
        const int cur = p & 1;
        const int nxt = cur ^ 1;

        float gr_n = 0.f, gz_n = 0.f, gn_n = 0.f;
        if (w == 0 && p + 1 < P_DIM) {
            long base = ((long)(p + 1) * B_DIM + b) * 768 + og;
            gr_n = gi[base]; gz_n = gi[base + 256]; gn_n = gi[base + 512];
        }

        // ---- poll: counters of my K-slice must reach p (per-lane element) ----
        {
            const unsigned sa = hbBase + (unsigned)(cur * 2080 + (32 * w + l) * 8);
            for (;;) {
                unsigned long long v;
                asm volatile("ld.volatile.shared.u64 %0, [%1];" : "=l"(v) : "r"(sa));
                if (__ballot_sync(0xffffffffu, (unsigned)(v >> 32) >= (unsigned)p)
                    == 0xffffffffu) break;
            }
        }

        // ---- GEMV: 16 broadcast LDS.128 (2 h-elements each) + 48 FFMA2 ----
        const unsigned pairBase = hbBase + (unsigned)(cur * 2080 + 32 * w * 8);
        unsigned long long ar = 0ull, az = 0ull, an = 0ull;
#pragma unroll
        for (int j = 0; j < 16; j++) {
            unsigned long long x, y;   // (cnt|h[2j]), (cnt|h[2j+1]) -- ALL lanes same addr
            asm volatile("ld.shared.v2.u64 {%0,%1}, [%2];"
                         : "=l"(x), "=l"(y) : "r"(pairBase + (unsigned)(j * 16)));
            float v0 = __uint_as_float((unsigned)x);
            float v1 = __uint_as_float((unsigned)y);
            unsigned long long hp;
            asm("mov.b64 %0, {%1,%2};" : "=l"(hp) : "f"(v0), "f"(v1));
            fma_f32x2(ar, wg2[0][j], hp);
            fma_f32x2(az, wg2[1][j], hp);
            fma_f32x2(an, wg2[2][j], hp);
        }
        {
            float x0, x1;
            asm("mov.b64 {%0,%1}, %2;" : "=f"(x0), "=f"(x1) : "l"(ar));
            part[w][0][l] = x0 + x1;
            asm("mov.b64 {%0,%1}, %2;" : "=f"(x0), "=f"(x1) : "l"(az));
            part[w][1][l] = x0 + x1;
            asm("mov.b64 {%0,%1}, %2;" : "=f"(x0), "=f"(x1) : "l"(an));
            part[w][2][l] = x0 + x1;
        }
        __syncthreads();   // partials visible; ONLY barrier in the loop

        if (w == 0) {
            float sr = b_r, sz = b_z, sn = b_n;
#pragma unroll
            for (int ww = 0; ww < 8; ww++) {
                sr += part[ww][0][l];
                sz += part[ww][1][l];
                sn += part[ww][2][l];
            }
            float r = fast_sigmoid(gr_c + sr);
            float z = fast_sigmoid(gz_c + sz);
            float n = fast_tanh(gn_c + r * sn);
            float hold = __uint_as_float((unsigned)hb64[cur][rank * 32 + l]);
            float hnew = (1.f - z) * n + z * hold;
            out[((long)p * B_DIM + b) * O_DIM + og] = hnew;

            if (p < P_DIM - 1) {
                unsigned long long pv =
                    (((unsigned long long)(unsigned)(p + 1)) << 32) |
                    (unsigned long long)__float_as_uint(hnew);
                const unsigned boff = (unsigned)(nxt * 2080);
#pragma unroll
                for (int c = 0; c < 8; c++)
                    asm volatile("st.relaxed.cluster.shared::cluster.u64 [%0], %1;"
                                 :: "r"(peerAddr[c] + boff), "l"(pv) : "memory");
            }
        }
        gr_c = gr_n; gz_c = gz_n; gn_c = gn_n;
    }
}

// ---------------- launch ----------------
extern "C" void kernel_launch(void* const* d_in, const int* in_sizes, int n_in,
                              void* d_out, int out_size)
{
    const float* passage  = (const float*)d_in[0];
    const float* question = (const float*)d_in[1];
    const float* Wuq      = (const float*)d_in[2];
    const float* Wup      = (const float*)d_in[3];
    const float* v        = (const float*)d_in[4];
    const float* Wg       = (const float*)d_in[5];
    const float* w_ih     = (const float*)d_in[6];
    const float* w_hh     = (const float*)d_in[7];
    const float* b_ih     = (const float*)d_in[8];
    const float* b_hh     = (const float*)d_in[9];
    float* out = (float*)d_out;

    void *pWp, *pWq, *pGcat, *pCg, *pGi;
    cudaGetSymbolAddress(&pWp, g_Wp);
    cudaGetSymbolAddress(&pWq, g_Wq);
    cudaGetSymbolAddress(&pGcat, g_gcat);
    cudaGetSymbolAddress(&pCg, g_cg);
    cudaGetSymbolAddress(&pGi, g_gi);

    dim3 blk(256);

    gemm_kernel<0><<<dim3(8192 / 128, 256 / 64), blk>>>(
        passage, Wup, nullptr, nullptr, (float*)pWp, 8192, 256, 256);
    gemm_kernel<0><<<dim3(1024 / 128, 256 / 64), blk>>>(
        question, Wuq, nullptr, nullptr, (float*)pWq, 1024, 256, 256);
    attn_kernel<<<dim3(P_DIM, B_DIM), blk>>>(question, passage, v);
    gemm_kernel<2><<<dim3(8192 / 128, 256 / 64), blk>>>(
        (const float*)pGcat, Wg + 256 * 512, nullptr, (const float*)pGcat,
        (float*)pCg, 8192, 256, 512);
    gemm_kernel<1><<<dim3(8192 / 128, 768 / 64), blk>>>(
        (const float*)pCg, w_ih, b_ih, nullptr, (float*)pGi, 8192, 768, 256);
    gru_kernel<<<128, 256>>>((const float*)pGi, w_hh, b_hh, out);
}

// round 12
// speedup vs baseline: 1.2208x; 1.2208x over previous
#include <cuda_runtime.h>

#define P_DIM 512
#define Q_DIM 64
#define B_DIM 16
#define E_DIM 256
#define H_DIM 256
#define O_DIM 256

// ---------------- scratch (static __device__, no allocation) ----------------
__device__ float g_Wp[P_DIM * B_DIM * H_DIM];          // (P,B,H)
__device__ float g_Wq[Q_DIM * B_DIM * H_DIM];          // (Q,B,H)
__device__ float g_gcat[P_DIM * B_DIM * 2 * E_DIM];    // (P,B,2E) = [passage | c]
__device__ float g_cg[P_DIM * B_DIM * E_DIM];          // c_gated
__device__ float g_gi[P_DIM * B_DIM * 3 * O_DIM];      // gi = x@w_ih^T + b_ih

// ---------------- math helpers ----------------
__device__ __forceinline__ float fast_tanh(float x) {
    float e = __expf(2.f * x);
    return 1.f - __fdividef(2.f, e + 1.f);
}
__device__ __forceinline__ float tanh_mufu(float x) {   // 1 MUFU op (sm_75+)
    float y;
    asm("tanh.approx.f32 %0, %1;" : "=f"(y) : "f"(x));
    return y;
}
__device__ __forceinline__ float fast_sigmoid(float x) {
    return __fdividef(1.f, 1.f + __expf(-x));
}
__device__ __forceinline__ unsigned smem_u32(const void* p) {
    return (unsigned)__cvta_generic_to_shared(p);
}
__device__ __forceinline__ void fma_f32x2(unsigned long long& acc,
                                          unsigned long long a,
                                          unsigned long long b) {
    asm("fma.rn.f32x2 %0, %1, %2, %0;" : "+l"(acc) : "l"(a), "l"(b));
}
__device__ __forceinline__ unsigned long long dup_f32x2(float x) {
    unsigned long long r;
    asm("mov.b64 %0, {%1,%1};" : "=l"(r) : "f"(x));
    return r;
}

// ---------------- GEMM v2 (R8 winner): C = epi(A @ W^T), f32x2, 128x64x16 ----------
// MODE 0: raw    MODE 1: + bias[n]    MODE 2: sigmoid(acc) * aux[row*512 + 256 + n]
template <int MODE>
__global__ __launch_bounds__(256) void gemm_kernel(
    const float* __restrict__ A, const float* __restrict__ W,
    const float* __restrict__ bias, const float* __restrict__ aux,
    float* __restrict__ C, int M, int N, int K)
{
    __shared__ __align__(16) float As[2][16 * 132];   // [k][m], stride 132
    __shared__ __align__(16) float Ws[2][16 * 68];    // [k][n], stride 68

    const int tid = threadIdx.x;
    const int m0 = blockIdx.x * 128;
    const int n0 = blockIdx.y * 64;
    const int tm = tid >> 4;    // 0..15 -> rows tm*8..+8
    const int tn = tid & 15;    // cols tn*4..+4
    const int K4 = K >> 2;
    const int NT = K >> 4;      // number of 16-wide k tiles

    const int ra = tid >> 2;            // 0..63  (A rows ra, ra+64)
    const int ca = tid & 3;             // float4 within 16-wide k tile
    const int kkA = ca * 4;

    unsigned long long acc2[4][4];
#pragma unroll
    for (int i = 0; i < 4; i++)
#pragma unroll
        for (int j = 0; j < 4; j++) acc2[i][j] = 0ull;

    const float4* A4 = (const float4*)A;
    const float4* W4 = (const float4*)W;

    float4 pa0, pa1, pw;
    pa0 = A4[(long)(m0 + ra) * K4 + ca];
    pa1 = A4[(long)(m0 + ra + 64) * K4 + ca];
    pw  = W4[(long)(n0 + ra) * K4 + ca];
    {
        As[0][(kkA + 0) * 132 + ra] = pa0.x; As[0][(kkA + 1) * 132 + ra] = pa0.y;
        As[0][(kkA + 2) * 132 + ra] = pa0.z; As[0][(kkA + 3) * 132 + ra] = pa0.w;
        As[0][(kkA + 0) * 132 + ra + 64] = pa1.x; As[0][(kkA + 1) * 132 + ra + 64] = pa1.y;
        As[0][(kkA + 2) * 132 + ra + 64] = pa1.z; As[0][(kkA + 3) * 132 + ra + 64] = pa1.w;
        Ws[0][(kkA + 0) * 68 + ra] = pw.x; Ws[0][(kkA + 1) * 68 + ra] = pw.y;
        Ws[0][(kkA + 2) * 68 + ra] = pw.z; Ws[0][(kkA + 3) * 68 + ra] = pw.w;
    }
    __syncthreads();

    for (int t = 0; t < NT; t++) {
        const int cur = t & 1, nxt = cur ^ 1;
        if (t + 1 < NT) {
            int kb = (t + 1) * 4;
            pa0 = A4[(long)(m0 + ra) * K4 + kb + ca];
            pa1 = A4[(long)(m0 + ra + 64) * K4 + kb + ca];
            pw  = W4[(long)(n0 + ra) * K4 + kb + ca];
        }
#pragma unroll
        for (int k = 0; k < 16; k++) {
            const ulonglong2* Ar =
                (const ulonglong2*)&As[cur][k * 132 + tm * 8];
            ulonglong2 a01 = Ar[0];
            ulonglong2 a23 = Ar[1];
            float4 wv = *(const float4*)&Ws[cur][k * 68 + tn * 4];
            unsigned long long w0 = dup_f32x2(wv.x), w1 = dup_f32x2(wv.y);
            unsigned long long w2 = dup_f32x2(wv.z), w3 = dup_f32x2(wv.w);
            fma_f32x2(acc2[0][0], a01.x, w0); fma_f32x2(acc2[0][1], a01.x, w1);
            fma_f32x2(acc2[0][2], a01.x, w2); fma_f32x2(acc2[0][3], a01.x, w3);
            fma_f32x2(acc2[1][0], a01.y, w0); fma_f32x2(acc2[1][1], a01.y, w1);
            fma_f32x2(acc2[1][2], a01.y, w2); fma_f32x2(acc2[1][3], a01.y, w3);
            fma_f32x2(acc2[2][0], a23.x, w0); fma_f32x2(acc2[2][1], a23.x, w1);
            fma_f32x2(acc2[2][2], a23.x, w2); fma_f32x2(acc2[2][3], a23.x, w3);
            fma_f32x2(acc2[3][0], a23.y, w0); fma_f32x2(acc2[3][1], a23.y, w1);
            fma_f32x2(acc2[3][2], a23.y, w2); fma_f32x2(acc2[3][3], a23.y, w3);
        }
        if (t + 1 < NT) {
            As[nxt][(kkA + 0) * 132 + ra] = pa0.x; As[nxt][(kkA + 1) * 132 + ra] = pa0.y;
            As[nxt][(kkA + 2) * 132 + ra] = pa0.z; As[nxt][(kkA + 3) * 132 + ra] = pa0.w;
            As[nxt][(kkA + 0) * 132 + ra + 64] = pa1.x; As[nxt][(kkA + 1) * 132 + ra + 64] = pa1.y;
            As[nxt][(kkA + 2) * 132 + ra + 64] = pa1.z; As[nxt][(kkA + 3) * 132 + ra + 64] = pa1.w;
            Ws[nxt][(kkA + 0) * 68 + ra] = pw.x; Ws[nxt][(kkA + 1) * 68 + ra] = pw.y;
            Ws[nxt][(kkA + 2) * 68 + ra] = pw.z; Ws[nxt][(kkA + 3) * 68 + ra] = pw.w;
        }
        __syncthreads();
    }

#pragma unroll
    for (int i2 = 0; i2 < 4; i2++) {
        float va[2][4];
#pragma unroll
        for (int j = 0; j < 4; j++)
            asm("mov.b64 {%0,%1}, %2;" : "=f"(va[0][j]), "=f"(va[1][j]) : "l"(acc2[i2][j]));
#pragma unroll
        for (int h = 0; h < 2; h++) {
            int row = m0 + tm * 8 + i2 * 2 + h;
            int col = n0 + tn * 4;
            float4 o;
            if (MODE == 0) {
                o = make_float4(va[h][0], va[h][1], va[h][2], va[h][3]);
            } else if (MODE == 1) {
                o = make_float4(va[h][0] + bias[col + 0], va[h][1] + bias[col + 1],
                                va[h][2] + bias[col + 2], va[h][3] + bias[col + 3]);
            } else {
                float4 g = *(const float4*)(aux + (long)row * 512 + 256 + col);
                o = make_float4(fast_sigmoid(va[h][0]) * g.x, fast_sigmoid(va[h][1]) * g.y,
                                fast_sigmoid(va[h][2]) * g.z, fast_sigmoid(va[h][3]) * g.w);
            }
            *(float4*)(&C[(long)row * N + col]) = o;
        }
    }
}

// ---------------- fused attention: MUFU.TANH scores -> softmax -> context ----------
__global__ __launch_bounds__(256) void attn_kernel(
    const float* __restrict__ question, const float* __restrict__ passage,
    const float* __restrict__ v)
{
    __shared__ float wp[256];
    __shared__ float vv[256];
    __shared__ float sc[64];

    const int p = blockIdx.x;
    const int b = blockIdx.y;
    const int tid = threadIdx.x;
    const int w = tid >> 5, l = tid & 31;

    wp[tid] = g_Wp[((long)p * B_DIM + b) * H_DIM + tid];
    vv[tid] = v[tid];
    __syncthreads();

#pragma unroll
    for (int qi = 0; qi < 8; qi++) {
        int q = w * 8 + qi;
        const float* wq = &g_Wq[((long)q * B_DIM + b) * H_DIM];
        float acc = 0.f;
#pragma unroll
        for (int j = 0; j < 8; j++) {
            int h = l + 32 * j;
            acc += vv[h] * tanh_mufu(wq[h] + wp[h]);   // 1 MUFU per tanh
        }
#pragma unroll
        for (int s = 16; s > 0; s >>= 1) acc += __shfl_xor_sync(0xffffffffu, acc, s);
        if (l == 0) sc[q] = acc;
    }
    __syncthreads();

    if (w == 0) {
        float s0 = sc[l], s1 = sc[32 + l];
        float m = fmaxf(s0, s1);
#pragma unroll
        for (int s = 16; s > 0; s >>= 1) m = fmaxf(m, __shfl_xor_sync(0xffffffffu, m, s));
        float e0 = __expf(s0 - m), e1 = __expf(s1 - m);
        float sum = e0 + e1;
#pragma unroll
        for (int s = 16; s > 0; s >>= 1) sum += __shfl_xor_sync(0xffffffffu, sum, s);
        float inv = __fdividef(1.f, sum);
        sc[l] = e0 * inv;
        sc[32 + l] = e1 * inv;
    }
    __syncthreads();

    float acc = 0.f;
#pragma unroll
    for (int q = 0; q < 64; q++)
        acc += sc[q] * question[((long)q * B_DIM + b) * E_DIM + tid];

    float* gr = &g_gcat[((long)p * B_DIM + b) * 2 * E_DIM];
    gr[256 + tid] = acc;
    gr[tid] = passage[((long)p * B_DIM + b) * E_DIM + tid];
}

// ---------------- GRU v6 (716.9us winner) + tail reorder (publish before STG) ------
__global__ void __cluster_dims__(8, 1, 1) __launch_bounds__(256, 1)
gru_kernel(const float* __restrict__ gi, const float* __restrict__ w_hh,
           const float* __restrict__ b_hh, float* __restrict__ out)
{
    __shared__ __align__(16) unsigned long long hb64[2][260];  // 256 slots + 4 pad, 2080B stride
    __shared__ float part[8][3][32];                           // [srcWarp][gate][output]

    const int tid = threadIdx.x;
    const int w = tid >> 5;            // K-slice warp 0..7
    const int l = tid & 31;            // output lane
    const int b = blockIdx.x >> 3;     // batch
    const int rank = blockIdx.x & 7;   // cluster rank
    const int og = rank * 32 + l;      // global output index

    // ---- weights: rows {g*256+og}, cols [32w, 32w+32) -> 48 f32x2 regs ----
    unsigned long long wg2[3][16];
#pragma unroll
    for (int g = 0; g < 3; g++) {
        const float4* p4 = (const float4*)(w_hh + (long)(g * 256 + og) * 256 + w * 32);
#pragma unroll
        for (int i = 0; i < 8; i++) {
            float4 t = p4[i];
            asm("mov.b64 %0, {%1,%2};" : "=l"(wg2[g][2*i])   : "f"(t.x), "f"(t.y));
            asm("mov.b64 %0, {%1,%2};" : "=l"(wg2[g][2*i+1]) : "f"(t.z), "f"(t.w));
        }
    }
    const float b_r = b_hh[0 * 256 + og];
    const float b_z = b_hh[1 * 256 + og];
    const float b_n = b_hh[2 * 256 + og];

    for (int i = tid; i < 2 * 260; i += 256) ((unsigned long long*)hb64)[i] = 0ull;

    unsigned peerAddr[8];
    {
        unsigned laddr = smem_u32(&hb64[0][rank * 32 + l]);
#pragma unroll
        for (int c = 0; c < 8; c++)
            asm("mapa.shared::cluster.u32 %0, %1, %2;" : "=r"(peerAddr[c]) : "r"(laddr), "r"(c));
    }
    __syncthreads();
    asm volatile("barrier.cluster.arrive.aligned;" ::: "memory");
    asm volatile("barrier.cluster.wait.aligned;" ::: "memory");

    const unsigned hbBase = smem_u32(&hb64[0][0]);

    // gi pipeline (warp 0 only), one step ahead
    float gr_c = 0.f, gz_c = 0.f, gn_c = 0.f;
    if (w == 0) {
        long base = ((long)0 * B_DIM + b) * 768 + og;
        gr_c = gi[base]; gz_c = gi[base + 256]; gn_c = gi[base + 512];
    }

    for (int p = 0; p < P_DIM; p++) {
        const int cur = p & 1;
        const int nxt = cur ^ 1;

        float gr_n = 0.f, gz_n = 0.f, gn_n = 0.f;
        if (w == 0 && p + 1 < P_DIM) {
            long base = ((long)(p + 1) * B_DIM + b) * 768 + og;
            gr_n = gi[base]; gz_n = gi[base + 256]; gn_n = gi[base + 512];
        }

        // ---- poll: counters of my K-slice must reach p (per-lane element) ----
        {
            const unsigned sa = hbBase + (unsigned)(cur * 2080 + (32 * w + l) * 8);
            for (;;) {
                unsigned long long v;
                asm volatile("ld.volatile.shared.u64 %0, [%1];" : "=l"(v) : "r"(sa));
                if (__ballot_sync(0xffffffffu, (unsigned)(v >> 32) >= (unsigned)p)
                    == 0xffffffffu) break;
            }
        }

        // ---- GEMV: 16 broadcast LDS.128 (2 h-elements each) + 48 FFMA2 ----
        const unsigned pairBase = hbBase + (unsigned)(cur * 2080 + 32 * w * 8);
        unsigned long long ar = 0ull, az = 0ull, an = 0ull;
#pragma unroll
        for (int j = 0; j < 16; j++) {
            unsigned long long x, y;   // (cnt|h[2j]), (cnt|h[2j+1]) -- ALL lanes same addr
            asm volatile("ld.shared.v2.u64 {%0,%1}, [%2];"
                         : "=l"(x), "=l"(y) : "r"(pairBase + (unsigned)(j * 16)));
            float v0 = __uint_as_float((unsigned)x);
            float v1 = __uint_as_float((unsigned)y);
            unsigned long long hp;
            asm("mov.b64 %0, {%1,%2};" : "=l"(hp) : "f"(v0), "f"(v1));
            fma_f32x2(ar, wg2[0][j], hp);
            fma_f32x2(az, wg2[1][j], hp);
            fma_f32x2(an, wg2[2][j], hp);
        }
        {
            float x0, x1;
            asm("mov.b64 {%0,%1}, %2;" : "=f"(x0), "=f"(x1) : "l"(ar));
            part[w][0][l] = x0 + x1;
            asm("mov.b64 {%0,%1}, %2;" : "=f"(x0), "=f"(x1) : "l"(az));
            part[w][1][l] = x0 + x1;
            asm("mov.b64 {%0,%1}, %2;" : "=f"(x0), "=f"(x1) : "l"(an));
            part[w][2][l] = x0 + x1;
        }
        __syncthreads();   // partials visible; ONLY barrier in the loop

        if (w == 0) {
            // hold read issued early (LDS latency overlapped with reduce)
            float hold = __uint_as_float((unsigned)hb64[cur][rank * 32 + l]);
            float sr = b_r, sz = b_z, sn = b_n;
#pragma unroll
            for (int ww = 0; ww < 8; ww++) {
                sr += part[ww][0][l];
                sz += part[ww][1][l];
                sn += part[ww][2][l];
            }
            float r = fast_sigmoid(gr_c + sr);
            float z = fast_sigmoid(gz_c + sz);
            float n = fast_tanh(gn_c + r * sn);
            float hnew = (1.f - z) * n + z * hold;

            // publish FIRST (starts the cross-CTA flight ASAP), then out store
            if (p < P_DIM - 1) {
                unsigned long long pv =
                    (((unsigned long long)(unsigned)(p + 1)) << 32) |
                    (unsigned long long)__float_as_uint(hnew);
                const unsigned boff = (unsigned)(nxt * 2080);
#pragma unroll
                for (int c = 0; c < 8; c++)
                    asm volatile("st.relaxed.cluster.shared::cluster.u64 [%0], %1;"
                                 :: "r"(peerAddr[c] + boff), "l"(pv) : "memory");
            }
            out[((long)p * B_DIM + b) * O_DIM + og] = hnew;
        }
        gr_c = gr_n; gz_c = gz_n; gn_c = gn_n;
    }
}

// ---------------- launch ----------------
extern "C" void kernel_launch(void* const* d_in, const int* in_sizes, int n_in,
                              void* d_out, int out_size)
{
    const float* passage  = (const float*)d_in[0];
    const float* question = (const float*)d_in[1];
    const float* Wuq      = (const float*)d_in[2];
    const float* Wup      = (const float*)d_in[3];
    const float* v        = (const float*)d_in[4];
    const float* Wg       = (const float*)d_in[5];
    const float* w_ih     = (const float*)d_in[6];
    const float* w_hh     = (const float*)d_in[7];
    const float* b_ih     = (const float*)d_in[8];
    const float* b_hh     = (const float*)d_in[9];
    float* out = (float*)d_out;

    void *pWp, *pWq, *pGcat, *pCg, *pGi;
    cudaGetSymbolAddress(&pWp, g_Wp);
    cudaGetSymbolAddress(&pWq, g_Wq);
    cudaGetSymbolAddress(&pGcat, g_gcat);
    cudaGetSymbolAddress(&pCg, g_cg);
    cudaGetSymbolAddress(&pGi, g_gi);

    dim3 blk(256);

    gemm_kernel<0><<<dim3(8192 / 128, 256 / 64), blk>>>(
        passage, Wup, nullptr, nullptr, (float*)pWp, 8192, 256, 256);
    gemm_kernel<0><<<dim3(1024 / 128, 256 / 64), blk>>>(
        question, Wuq, nullptr, nullptr, (float*)pWq, 1024, 256, 256);
    attn_kernel<<<dim3(P_DIM, B_DIM), blk>>>(question, passage, v);
    gemm_kernel<2><<<dim3(8192 / 128, 256 / 64), blk>>>(
        (const float*)pGcat, Wg + 256 * 512, nullptr, (const float*)pGcat,
        (float*)pCg, 8192, 256, 512);
    gemm_kernel<1><<<dim3(8192 / 128, 768 / 64), blk>>>(
        (const float*)pCg, w_ih, b_ih, nullptr, (float*)pGi, 8192, 768, 256);
    gru_kernel<<<128, 256>>>((const float*)pGi, w_hh, b_hh, out);
}

// round 13
// speedup vs baseline: 1.4937x; 1.2236x over previous
#include <cuda_runtime.h>

#define P_DIM 512
#define Q_DIM 64
#define B_DIM 16
#define E_DIM 256
#define H_DIM 256
#define O_DIM 256

// ---------------- scratch (static __device__, no allocation) ----------------
__device__ float g_Wp[P_DIM * B_DIM * H_DIM];          // (P,B,H)
__device__ float g_Wq[Q_DIM * B_DIM * H_DIM];          // (Q,B,H)
__device__ float g_gcat[P_DIM * B_DIM * 2 * E_DIM];    // (P,B,2E) = [passage | c]
__device__ float g_cg[P_DIM * B_DIM * E_DIM];          // c_gated
__device__ float g_gi[P_DIM * B_DIM * 3 * O_DIM];      // gi = x@w_ih^T + b_ih

// ---------------- math helpers ----------------
__device__ __forceinline__ float fast_tanh(float x) {
    float e = __expf(2.f * x);
    return 1.f - __fdividef(2.f, e + 1.f);
}
__device__ __forceinline__ float tanh_mufu(float x) {   // 1 MUFU op
    float y;
    asm("tanh.approx.f32 %0, %1;" : "=f"(y) : "f"(x));
    return y;
}
__device__ __forceinline__ float fast_sigmoid(float x) {
    return __fdividef(1.f, 1.f + __expf(-x));
}
__device__ __forceinline__ unsigned smem_u32(const void* p) {
    return (unsigned)__cvta_generic_to_shared(p);
}
__device__ __forceinline__ void fma_f32x2(unsigned long long& acc,
                                          unsigned long long a,
                                          unsigned long long b) {
    asm("fma.rn.f32x2 %0, %1, %2, %0;" : "+l"(acc) : "l"(a), "l"(b));
}
__device__ __forceinline__ unsigned long long dup_f32x2(float x) {
    unsigned long long r;
    asm("mov.b64 %0, {%1,%1};" : "=l"(r) : "f"(x));
    return r;
}

// ---------------- GEMM v2 (R8 winner): C = epi(A @ W^T), f32x2, 128x64x16 ----------
// MODE 0: raw    MODE 1: + bias[n]    MODE 2: sigmoid(acc) * aux[row*512 + 256 + n]
template <int MODE>
__global__ __launch_bounds__(256) void gemm_kernel(
    const float* __restrict__ A, const float* __restrict__ W,
    const float* __restrict__ bias, const float* __restrict__ aux,
    float* __restrict__ C, int M, int N, int K)
{
    __shared__ __align__(16) float As[2][16 * 132];   // [k][m], stride 132
    __shared__ __align__(16) float Ws[2][16 * 68];    // [k][n], stride 68

    const int tid = threadIdx.x;
    const int m0 = blockIdx.x * 128;
    const int n0 = blockIdx.y * 64;
    const int tm = tid >> 4;
    const int tn = tid & 15;
    const int K4 = K >> 2;
    const int NT = K >> 4;

    const int ra = tid >> 2;
    const int ca = tid & 3;
    const int kkA = ca * 4;

    unsigned long long acc2[4][4];
#pragma unroll
    for (int i = 0; i < 4; i++)
#pragma unroll
        for (int j = 0; j < 4; j++) acc2[i][j] = 0ull;

    const float4* A4 = (const float4*)A;
    const float4* W4 = (const float4*)W;

    float4 pa0, pa1, pw;
    pa0 = A4[(long)(m0 + ra) * K4 + ca];
    pa1 = A4[(long)(m0 + ra + 64) * K4 + ca];
    pw  = W4[(long)(n0 + ra) * K4 + ca];
    {
        As[0][(kkA + 0) * 132 + ra] = pa0.x; As[0][(kkA + 1) * 132 + ra] = pa0.y;
        As[0][(kkA + 2) * 132 + ra] = pa0.z; As[0][(kkA + 3) * 132 + ra] = pa0.w;
        As[0][(kkA + 0) * 132 + ra + 64] = pa1.x; As[0][(kkA + 1) * 132 + ra + 64] = pa1.y;
        As[0][(kkA + 2) * 132 + ra + 64] = pa1.z; As[0][(kkA + 3) * 132 + ra + 64] = pa1.w;
        Ws[0][(kkA + 0) * 68 + ra] = pw.x; Ws[0][(kkA + 1) * 68 + ra] = pw.y;
        Ws[0][(kkA + 2) * 68 + ra] = pw.z; Ws[0][(kkA + 3) * 68 + ra] = pw.w;
    }
    __syncthreads();

    for (int t = 0; t < NT; t++) {
        const int cur = t & 1, nxt = cur ^ 1;
        if (t + 1 < NT) {
            int kb = (t + 1) * 4;
            pa0 = A4[(long)(m0 + ra) * K4 + kb + ca];
            pa1 = A4[(long)(m0 + ra + 64) * K4 + kb + ca];
            pw  = W4[(long)(n0 + ra) * K4 + kb + ca];
        }
#pragma unroll
        for (int k = 0; k < 16; k++) {
            const ulonglong2* Ar =
                (const ulonglong2*)&As[cur][k * 132 + tm * 8];
            ulonglong2 a01 = Ar[0];
            ulonglong2 a23 = Ar[1];
            float4 wv = *(const float4*)&Ws[cur][k * 68 + tn * 4];
            unsigned long long w0 = dup_f32x2(wv.x), w1 = dup_f32x2(wv.y);
            unsigned long long w2 = dup_f32x2(wv.z), w3 = dup_f32x2(wv.w);
            fma_f32x2(acc2[0][0], a01.x, w0); fma_f32x2(acc2[0][1], a01.x, w1);
            fma_f32x2(acc2[0][2], a01.x, w2); fma_f32x2(acc2[0][3], a01.x, w3);
            fma_f32x2(acc2[1][0], a01.y, w0); fma_f32x2(acc2[1][1], a01.y, w1);
            fma_f32x2(acc2[1][2], a01.y, w2); fma_f32x2(acc2[1][3], a01.y, w3);
            fma_f32x2(acc2[2][0], a23.x, w0); fma_f32x2(acc2[2][1], a23.x, w1);
            fma_f32x2(acc2[2][2], a23.x, w2); fma_f32x2(acc2[2][3], a23.x, w3);
            fma_f32x2(acc2[3][0], a23.y, w0); fma_f32x2(acc2[3][1], a23.y, w1);
            fma_f32x2(acc2[3][2], a23.y, w2); fma_f32x2(acc2[3][3], a23.y, w3);
        }
        if (t + 1 < NT) {
            As[nxt][(kkA + 0) * 132 + ra] = pa0.x; As[nxt][(kkA + 1) * 132 + ra] = pa0.y;
            As[nxt][(kkA + 2) * 132 + ra] = pa0.z; As[nxt][(kkA + 3) * 132 + ra] = pa0.w;
            As[nxt][(kkA + 0) * 132 + ra + 64] = pa1.x; As[nxt][(kkA + 1) * 132 + ra + 64] = pa1.y;
            As[nxt][(kkA + 2) * 132 + ra + 64] = pa1.z; As[nxt][(kkA + 3) * 132 + ra + 64] = pa1.w;
            Ws[nxt][(kkA + 0) * 68 + ra] = pw.x; Ws[nxt][(kkA + 1) * 68 + ra] = pw.y;
            Ws[nxt][(kkA + 2) * 68 + ra] = pw.z; Ws[nxt][(kkA + 3) * 68 + ra] = pw.w;
        }
        __syncthreads();
    }

#pragma unroll
    for (int i2 = 0; i2 < 4; i2++) {
        float va[2][4];
#pragma unroll
        for (int j = 0; j < 4; j++)
            asm("mov.b64 {%0,%1}, %2;" : "=f"(va[0][j]), "=f"(va[1][j]) : "l"(acc2[i2][j]));
#pragma unroll
        for (int h = 0; h < 2; h++) {
            int row = m0 + tm * 8 + i2 * 2 + h;
            int col = n0 + tn * 4;
            float4 o;
            if (MODE == 0) {
                o = make_float4(va[h][0], va[h][1], va[h][2], va[h][3]);
            } else if (MODE == 1) {
                o = make_float4(va[h][0] + bias[col + 0], va[h][1] + bias[col + 1],
                                va[h][2] + bias[col + 2], va[h][3] + bias[col + 3]);
            } else {
                float4 g = *(const float4*)(aux + (long)row * 512 + 256 + col);
                o = make_float4(fast_sigmoid(va[h][0]) * g.x, fast_sigmoid(va[h][1]) * g.y,
                                fast_sigmoid(va[h][2]) * g.z, fast_sigmoid(va[h][3]) * g.w);
            }
            *(float4*)(&C[(long)row * N + col]) = o;
        }
    }
}

// ---------------- fused attention: MUFU.TANH scores -> softmax -> context ----------
__global__ __launch_bounds__(256) void attn_kernel(
    const float* __restrict__ question, const float* __restrict__ passage,
    const float* __restrict__ v)
{
    __shared__ float wp[256];
    __shared__ float vv[256];
    __shared__ float sc[64];

    const int p = blockIdx.x;
    const int b = blockIdx.y;
    const int tid = threadIdx.x;
    const int w = tid >> 5, l = tid & 31;

    wp[tid] = g_Wp[((long)p * B_DIM + b) * H_DIM + tid];
    vv[tid] = v[tid];
    __syncthreads();

#pragma unroll
    for (int qi = 0; qi < 8; qi++) {
        int q = w * 8 + qi;
        const float* wq = &g_Wq[((long)q * B_DIM + b) * H_DIM];
        float acc = 0.f;
#pragma unroll
        for (int j = 0; j < 8; j++) {
            int h = l + 32 * j;
            acc += vv[h] * tanh_mufu(wq[h] + wp[h]);
        }
#pragma unroll
        for (int s = 16; s > 0; s >>= 1) acc += __shfl_xor_sync(0xffffffffu, acc, s);
        if (l == 0) sc[q] = acc;
    }
    __syncthreads();

    if (w == 0) {
        float s0 = sc[l], s1 = sc[32 + l];
        float m = fmaxf(s0, s1);
#pragma unroll
        for (int s = 16; s > 0; s >>= 1) m = fmaxf(m, __shfl_xor_sync(0xffffffffu, m, s));
        float e0 = __expf(s0 - m), e1 = __expf(s1 - m);
        float sum = e0 + e1;
#pragma unroll
        for (int s = 16; s > 0; s >>= 1) sum += __shfl_xor_sync(0xffffffffu, sum, s);
        float inv = __fdividef(1.f, sum);
        sc[l] = e0 * inv;
        sc[32 + l] = e1 * inv;
    }
    __syncthreads();

    float acc = 0.f;
#pragma unroll
    for (int q = 0; q < 64; q++)
        acc += sc[q] * question[((long)q * B_DIM + b) * E_DIM + tid];

    float* gr = &g_gcat[((long)p * B_DIM + b) * 2 * E_DIM];
    gr[256 + tid] = acc;
    gr[tid] = passage[((long)p * B_DIM + b) * E_DIM + tid];
}

// ---------------- GRU v10: v6 protocol x2 batches per cluster, parallel tails ------
// 8 clusters x 8 CTAs; cluster c handles batches 2c, 2c+1. Weights (batch-
// invariant) shared in regs. Per step: each warp runs GEMV-A then GEMV-B
// (B's compute hides A's publish flight), one barrier, then warp0 does tail-A
// and warp1 does tail-B in parallel. Per-batch protocol identical to v6.
__global__ void __cluster_dims__(8, 1, 1) __launch_bounds__(256, 1)
gru_kernel(const float* __restrict__ gi, const float* __restrict__ w_hh,
           const float* __restrict__ b_hh, float* __restrict__ out)
{
    __shared__ __align__(16) unsigned long long hb64[2][2][260]; // [batch][buf][slot]
    __shared__ float part[2][8][3][32];                          // [batch][srcWarp][gate][lane]

    const int tid = threadIdx.x;
    const int w = tid >> 5;            // K-slice warp 0..7
    const int l = tid & 31;            // output lane
    const int b0 = (blockIdx.x >> 3) * 2;   // first batch of this cluster
    const int rank = blockIdx.x & 7;   // cluster rank
    const int og = rank * 32 + l;      // global output index (same for both batches)

    // ---- weights: rows {g*256+og}, cols [32w, 32w+32) -> 48 f32x2 regs (shared) ----
    unsigned long long wg2[3][16];
#pragma unroll
    for (int g = 0; g < 3; g++) {
        const float4* p4 = (const float4*)(w_hh + (long)(g * 256 + og) * 256 + w * 32);
#pragma unroll
        for (int i = 0; i < 8; i++) {
            float4 t = p4[i];
            asm("mov.b64 %0, {%1,%2};" : "=l"(wg2[g][2*i])   : "f"(t.x), "f"(t.y));
            asm("mov.b64 %0, {%1,%2};" : "=l"(wg2[g][2*i+1]) : "f"(t.z), "f"(t.w));
        }
    }
    const float b_r = b_hh[0 * 256 + og];
    const float b_z = b_hh[1 * 256 + og];
    const float b_n = b_hh[2 * 256 + og];

    for (int i = tid; i < 2 * 2 * 260; i += 256) ((unsigned long long*)hb64)[i] = 0ull;

    // publish addresses: warp tw in {0,1} sends its batch's h[og] to all 8 peers
    unsigned peerAddr[8];
    {
        int bidx = w & 1;   // only meaningful for w<2; harmless otherwise
        unsigned laddr = smem_u32(&hb64[bidx][0][rank * 32 + l]);
#pragma unroll
        for (int c = 0; c < 8; c++)
            asm("mapa.shared::cluster.u32 %0, %1, %2;" : "=r"(peerAddr[c]) : "r"(laddr), "r"(c));
    }
    __syncthreads();
    asm volatile("barrier.cluster.arrive.aligned;" ::: "memory");
    asm volatile("barrier.cluster.wait.aligned;" ::: "memory");

    const unsigned hbBase = smem_u32(&hb64[0][0][0]);   // batch stride 4160B, buf stride 2080B

    // gi pipeline: warp 0 carries batch A's gi, warp 1 carries batch B's (one step ahead)
    float gr_c = 0.f, gz_c = 0.f, gn_c = 0.f;
    if (w < 2) {
        long base = ((long)0 * B_DIM + (b0 + w)) * 768 + og;
        gr_c = gi[base]; gz_c = gi[base + 256]; gn_c = gi[base + 512];
    }

    for (int p = 0; p < P_DIM; p++) {
        const int cur = p & 1;
        const int nxt = cur ^ 1;

        float gr_n = 0.f, gz_n = 0.f, gn_n = 0.f;
        if (w < 2 && p + 1 < P_DIM) {
            long base = ((long)(p + 1) * B_DIM + (b0 + w)) * 768 + og;
            gr_n = gi[base]; gz_n = gi[base + 256]; gn_n = gi[base + 512];
        }

        // ---- per batch: poll, GEMV, partials (A then B) ----
#pragma unroll
        for (int bb = 0; bb < 2; bb++) {
            const unsigned bOff = (unsigned)(bb * 4160 + cur * 2080);
            // poll: counters of my K-slice must reach p
            {
                const unsigned sa = hbBase + bOff + (unsigned)((32 * w + l) * 8);
                for (;;) {
                    unsigned long long v;
                    asm volatile("ld.volatile.shared.u64 %0, [%1];" : "=l"(v) : "r"(sa));
                    if (__ballot_sync(0xffffffffu, (unsigned)(v >> 32) >= (unsigned)p)
                        == 0xffffffffu) break;
                }
            }
            // GEMV: 16 broadcast LDS.128 + 48 FFMA2
            const unsigned pairBase = hbBase + bOff + (unsigned)(32 * w * 8);
            unsigned long long ar = 0ull, az = 0ull, an = 0ull;
#pragma unroll
            for (int j = 0; j < 16; j++) {
                unsigned long long x, y;
                asm volatile("ld.shared.v2.u64 {%0,%1}, [%2];"
                             : "=l"(x), "=l"(y) : "r"(pairBase + (unsigned)(j * 16)));
                float v0 = __uint_as_float((unsigned)x);
                float v1 = __uint_as_float((unsigned)y);
                unsigned long long hp;
                asm("mov.b64 %0, {%1,%2};" : "=l"(hp) : "f"(v0), "f"(v1));
                fma_f32x2(ar, wg2[0][j], hp);
                fma_f32x2(az, wg2[1][j], hp);
                fma_f32x2(an, wg2[2][j], hp);
            }
            float x0, x1;
            asm("mov.b64 {%0,%1}, %2;" : "=f"(x0), "=f"(x1) : "l"(ar));
            part[bb][w][0][l] = x0 + x1;
            asm("mov.b64 {%0,%1}, %2;" : "=f"(x0), "=f"(x1) : "l"(az));
            part[bb][w][1][l] = x0 + x1;
            asm("mov.b64 {%0,%1}, %2;" : "=f"(x0), "=f"(x1) : "l"(an));
            part[bb][w][2][l] = x0 + x1;
        }
        __syncthreads();   // partials (both batches) visible; ONLY barrier in the loop

        if (w < 2) {       // warp 0 -> batch A tail, warp 1 -> batch B tail (parallel)
            const int bb = w;
            float hold = __uint_as_float(
                (unsigned)hb64[bb][cur][rank * 32 + l]);
            float sr = b_r, sz = b_z, sn = b_n;
#pragma unroll
            for (int ww = 0; ww < 8; ww++) {
                sr += part[bb][ww][0][l];
                sz += part[bb][ww][1][l];
                sn += part[bb][ww][2][l];
            }
            float r = fast_sigmoid(gr_c + sr);
            float z = fast_sigmoid(gz_c + sz);
            float n = fast_tanh(gn_c + r * sn);
            float hnew = (1.f - z) * n + z * hold;

            if (p < P_DIM - 1) {
                unsigned long long pv =
                    (((unsigned long long)(unsigned)(p + 1)) << 32) |
                    (unsigned long long)__float_as_uint(hnew);
                const unsigned boff = (unsigned)(nxt * 2080);
#pragma unroll
                for (int c = 0; c < 8; c++)
                    asm volatile("st.relaxed.cluster.shared::cluster.u64 [%0], %1;"
                                 :: "r"(peerAddr[c] + boff), "l"(pv) : "memory");
            }
            out[((long)p * B_DIM + (b0 + bb)) * O_DIM + og] = hnew;
        }
        gr_c = gr_n; gz_c = gz_n; gn_c = gn_n;
    }
}

// ---------------- launch ----------------
extern "C" void kernel_launch(void* const* d_in, const int* in_sizes, int n_in,
                              void* d_out, int out_size)
{
    const float* passage  = (const float*)d_in[0];
    const float* question = (const float*)d_in[1];
    const float* Wuq      = (const float*)d_in[2];
    const float* Wup      = (const float*)d_in[3];
    const float* v        = (const float*)d_in[4];
    const float* Wg       = (const float*)d_in[5];
    const float* w_ih     = (const float*)d_in[6];
    const float* w_hh     = (const float*)d_in[7];
    const float* b_ih     = (const float*)d_in[8];
    const float* b_hh     = (const float*)d_in[9];
    float* out = (float*)d_out;

    void *pWp, *pWq, *pGcat, *pCg, *pGi;
    cudaGetSymbolAddress(&pWp, g_Wp);
    cudaGetSymbolAddress(&pWq, g_Wq);
    cudaGetSymbolAddress(&pGcat, g_gcat);
    cudaGetSymbolAddress(&pCg, g_cg);
    cudaGetSymbolAddress(&pGi, g_gi);

    dim3 blk(256);

    gemm_kernel<0><<<dim3(8192 / 128, 256 / 64), blk>>>(
        passage, Wup, nullptr, nullptr, (float*)pWp, 8192, 256, 256);
    gemm_kernel<0><<<dim3(1024 / 128, 256 / 64), blk>>>(
        question, Wuq, nullptr, nullptr, (float*)pWq, 1024, 256, 256);
    attn_kernel<<<dim3(P_DIM, B_DIM), blk>>>(question, passage, v);
    gemm_kernel<2><<<dim3(8192 / 128, 256 / 64), blk>>>(
        (const float*)pGcat, Wg + 256 * 512, nullptr, (const float*)pGcat,
        (float*)pCg, 8192, 256, 512);
    gemm_kernel<1><<<dim3(8192 / 128, 768 / 64), blk>>>(
        (const float*)pCg, w_ih, b_ih, nullptr, (float*)pGi, 8192, 768, 256);
    // 8 clusters x 8 CTAs, 2 batches per cluster
    gru_kernel<<<64, 256>>>((const float*)pGi, w_hh, b_hh, out);
}